// round 4
// baseline (speedup 1.0000x reference)
#include <cuda_runtime.h>
#include <cuda_bf16.h>

// MQCNN layer, closed form (R0 derivation):
// z = (6cos(a) + cos(a+s1)+cos(a+s2)+cos(a+s3)+cos(a+s4)+cos(a+s5)
//    + cos(a+s1+s3)+cos(a+s2+s5)+cos(a+s2+s3+s4)+cos(a+s1+s4+s5)
//    + cos(a+s1+s2+s3+s4+s5)) / 16
// U3_w provably dead (unitaries on wire 6 preserve the wire-4 marginal).
//
// R4: 4 outputs per thread, 12 front-batched LDG.128 (MLP=12), float4 store.
// 32768 threads = grid 128 x block 256 -> ONE wave, one CTA/SM: the DRAM
// round-trip is exposed exactly once chip-wide, and the total issued
// instruction stream is minimized (indexing amortized over 4 outputs).

#define CH_STRIDE (128 * 128)
#define N_THREADS (32 * 64 * 16)   // 32768 threads, 4 outputs each

__device__ __forceinline__ float eval_patch(
    float c0r0x, float c0r0y, float c0r1x, float c0r1y,
    float c1r0x, float c1r0y, float c1r1x, float c1r1y,
    float c2r0x, float c2r0y, float c2r1x, float c2r1y)
{
    float a  = c0r0x + c1r0x + c2r0x;
    float s1 = c0r0y + c1r1x;
    float s2 = c0r1x + c2r1y;
    float s3 = c0r1y;
    float s4 = c1r0y + c2r1x;
    float s5 = c1r1y + c2r0y;

    float s13 = s1 + s3;
    float s45 = s4 + s5;

    float sum = 6.0f * __cosf(a);
    sum += __cosf(a + s1);
    sum += __cosf(a + s2);
    sum += __cosf(a + s3);
    sum += __cosf(a + s4);
    sum += __cosf(a + s5);
    sum += __cosf(a + s13);
    sum += __cosf(a + s2 + s5);
    sum += __cosf(a + s2 + s3 + s4);
    sum += __cosf(a + s1 + s45);
    sum += __cosf(a + s13 + s2 + s45);
    return sum * 0.0625f;
}

__global__ __launch_bounds__(256) void mqcnn_kernel(
    const float* __restrict__ x, float* __restrict__ out)
{
    int tid = blockIdx.x * blockDim.x + threadIdx.x;

    int kq = tid & 15;          // quad index: covers output cols 4kq..4kq+3
    int j  = (tid >> 4) & 63;
    int b  = tid >> 10;

    // input cols 8kq..8kq+7, rows 2j and 2j+1, channels 0..2
    const float* base = x + (size_t)b * (3 * CH_STRIDE)
                          + (size_t)(2 * j) * 128 + 8 * kq;

    // 12 independent 16B loads, all issued before any use (MLP=12)
    float4 a00 = *reinterpret_cast<const float4*>(base);
    float4 b00 = *reinterpret_cast<const float4*>(base + 4);
    float4 a01 = *reinterpret_cast<const float4*>(base + 128);
    float4 b01 = *reinterpret_cast<const float4*>(base + 132);
    float4 a10 = *reinterpret_cast<const float4*>(base + CH_STRIDE);
    float4 b10 = *reinterpret_cast<const float4*>(base + CH_STRIDE + 4);
    float4 a11 = *reinterpret_cast<const float4*>(base + CH_STRIDE + 128);
    float4 b11 = *reinterpret_cast<const float4*>(base + CH_STRIDE + 132);
    float4 a20 = *reinterpret_cast<const float4*>(base + 2 * CH_STRIDE);
    float4 b20 = *reinterpret_cast<const float4*>(base + 2 * CH_STRIDE + 4);
    float4 a21 = *reinterpret_cast<const float4*>(base + 2 * CH_STRIDE + 128);
    float4 b21 = *reinterpret_cast<const float4*>(base + 2 * CH_STRIDE + 132);

    float4 z;
    z.x = eval_patch(a00.x, a00.y, a01.x, a01.y,
                     a10.x, a10.y, a11.x, a11.y,
                     a20.x, a20.y, a21.x, a21.y);
    z.y = eval_patch(a00.z, a00.w, a01.z, a01.w,
                     a10.z, a10.w, a11.z, a11.w,
                     a20.z, a20.w, a21.z, a21.w);
    z.z = eval_patch(b00.x, b00.y, b01.x, b01.y,
                     b10.x, b10.y, b11.x, b11.y,
                     b20.x, b20.y, b21.x, b21.y);
    z.w = eval_patch(b00.z, b00.w, b01.z, b01.w,
                     b10.z, b10.w, b11.z, b11.w,
                     b20.z, b20.w, b21.z, b21.w);

    int o = (b << 12) + (j << 6) + (kq << 2);
    *reinterpret_cast<float4*>(out + o) = z;
}

extern "C" void kernel_launch(void* const* d_in, const int* in_sizes, int n_in,
                              void* d_out, int out_size) {
    const float* x = (const float*)d_in[0];   // [32,3,128,128] float32
    float* out = (float*)d_out;               // [32,1,64,64] float32
    mqcnn_kernel<<<N_THREADS / 256, 256>>>(x, out);
}

// round 5
// speedup vs baseline: 1.2455x; 1.2455x over previous
#include <cuda_runtime.h>
#include <cuda_bf16.h>

// MQCNN layer, closed form (R0 derivation):
// z = (6cos(A) + cos(A+s1)+cos(A+s2)+cos(A+s3)+cos(A+s4)+cos(A+s5)
//    + cos(A+s1+s3)+cos(A+s2+s5)+cos(A+s2+s3+s4)+cos(A+s1+s4+s5)
//    + cos(A+s1+s2+s3+s4+s5)) / 16
// U3_w provably dead (unitaries on wire 6 preserve the wire-4 marginal).
//
// R5: pair-split (2 threads/output, lane parity = patch row) at max
// occupancy: 262144 threads, block 512, grid 512 (~86% theoretical occ,
// half R1's CTA count). Exchange trimmed to 4 bfly shuffles + 1 combine:
//   lane0 local: a (full row-0 channel sum), c0r0.y, c1r0.y, c2r0.y
//   lane1 local: s2 = c0r1.x + c2r1.y, s3 = c0r1.y, c1r1.x, c2r1.x, c1r1.y
// Cos split 5/6: lane0: 6cosA, A+s1, A+s4, A+s5, A+s2
//                lane1: A+s3, A+s13, A+s2+s5, A+s2+s3+s4, A+s1+s45, A+all

#define CH_STRIDE (128 * 128)
#define N_THREADS (32 * 64 * 64 * 2)   // 2 threads per output

__global__ __launch_bounds__(512) void mqcnn_kernel(
    const float* __restrict__ x, float* __restrict__ out)
{
    int tid = blockIdx.x * blockDim.x + threadIdx.x;
    int o = tid >> 1;          // output index
    int p = tid & 1;           // 0: row 2j, 1: row 2j+1
    bool pp = (p != 0);

    int k = o & 63;
    int j = (o >> 6) & 63;
    int b = o >> 12;

    // this thread's row (2j+p), cols 2k..2k+1, across 3 channels
    const float* base = x + (size_t)b * (3 * CH_STRIDE)
                          + (size_t)(2 * j + p) * 128 + 2 * k;
    float2 L0 = *reinterpret_cast<const float2*>(base);                 // ch0
    float2 L1 = *reinterpret_cast<const float2*>(base + CH_STRIDE);     // ch1
    float2 L2 = *reinterpret_cast<const float2*>(base + 2 * CH_STRIDE); // ch2

    // lane-local precompute
    float a_l  = L0.x + L1.x + L2.x;   // lane0: A
    float s2_l = L0.x + L2.y;          // lane1: s2
    float s3_l = L0.y;                 // lane1: s3

    // 4-slot butterfly exchange (xor 1)
    const unsigned m = 0xFFFFFFFFu;
    float o0 = pp ? L1.x : a_l;    // lane0 sends A,     lane1 sends c1r1.x
    float o1 = pp ? L2.x : L0.y;   // lane0 sends c0r0.y,lane1 sends c2r1.x
    float o2 = L1.y;               // symmetric: c1r0.y <-> c1r1.y (no select)
    float o3 = pp ? s2_l : L2.y;   // lane0 sends c2r0.y,lane1 sends s2
    float r0 = __shfl_xor_sync(m, o0, 1);
    float r1 = __shfl_xor_sync(m, o1, 1);
    float r2 = __shfl_xor_sync(m, o2, 1);
    float r3 = __shfl_xor_sync(m, o3, 1);

    // reconstruct A, s1, s4, s5 on both lanes; s2 on lane0; s2,s3 on lane1
    float A  = pp ? r0 : a_l;
    float s1 = pp ? (r1 + L1.x) : (L0.y + r0);
    float s4 = pp ? (r2 + L2.x) : (L1.y + r1);
    float s5 = pp ? (r3 + L1.y) : (L2.y + r2);
    float s2 = pp ? s2_l : r3;
    float s3 = s3_l;               // valid on lane1 only (unused on lane0)

    // 6 cosine slots; lane0's last slot is weight-6 cos(A), lane1 gets 6 terms
    float e0 = pp ? (A + s3)                     : A;
    float e1 = pp ? (A + s1 + s3)                : (A + s1);
    float e2 = pp ? (A + s2 + s5)                : (A + s2);
    float e3 = pp ? (A + s2 + s3 + s4)           : (A + s4);
    float e4 = pp ? (A + s1 + s4 + s5)           : (A + s5);
    float e5 = pp ? (A + s1 + s2 + s3 + s4 + s5) : A;
    float w5 = pp ? 1.0f : 5.0f;   // lane0: cos(A) appears 1 (e0) + 5 (e5) = 6

    float sum = __cosf(e0) + __cosf(e1) + __cosf(e2)
              + __cosf(e3) + __cosf(e4) + w5 * __cosf(e5);

    sum += __shfl_xor_sync(m, sum, 1);
    if (!pp) out[o] = sum * 0.0625f;
}

extern "C" void kernel_launch(void* const* d_in, const int* in_sizes, int n_in,
                              void* d_out, int out_size) {
    const float* x = (const float*)d_in[0];   // [32,3,128,128] float32
    float* out = (float*)d_out;               // [32,1,64,64] float32
    mqcnn_kernel<<<N_THREADS / 512, 512>>>(x, out);
}

// round 6
// speedup vs baseline: 1.3413x; 1.0769x over previous
#include <cuda_runtime.h>
#include <cuda_bf16.h>

// MQCNN layer, closed form (R0 derivation):
// Per patch, wires 0-3 are an H-superposition of 16 control branches; the 12
// controlled-RY on wire 4 compose additively per branch; the 24 controlled-U3
// + H act only on wires 5,6 and preserve the wire-4 marginal (U3_w is dead).
// <Z>_4 = (1/16) sum_b cos(theta_b), which collapses to 11 distinct cosines:
// z = (6cos(a) + cos(a+s1)+cos(a+s2)+cos(a+s3)+cos(a+s4)+cos(a+s5)
//    + cos(a+s1+s3)+cos(a+s2+s5)+cos(a+s2+s3+s4)+cos(a+s1+s4+s5)
//    + cos(a+s1+s2+s3+s4+s5)) / 16
//
// R6: terminal configuration. R1-R5 established a hard ~5.4us kernel floor
// (launch overhead + one memory round trip) invariant across occ 21-71%,
// MLP 3-12, 2x instruction-count range. Best harness dur_us came from the
// R0 shape (grid 512 x block 256, 1 output/thread, 6x LDG.64). This is that
// kernel with dead code removed (exact-cover grid -> no bounds check) and
// CSE'd cosine arguments.

#define CH_STRIDE (128 * 128)
#define N_OUT (32 * 64 * 64)

__global__ __launch_bounds__(256) void mqcnn_kernel(
    const float* __restrict__ x, float* __restrict__ out)
{
    int tid = blockIdx.x * blockDim.x + threadIdx.x;

    int k = tid & 63;
    int j = (tid >> 6) & 63;
    int b = tid >> 12;

    // x[b, 0, 2j, 2k]
    const float* base = x + (size_t)b * (3 * CH_STRIDE)
                          + (size_t)j * 256 + 2 * k;

    float2 c0r0 = *reinterpret_cast<const float2*>(base);
    float2 c0r1 = *reinterpret_cast<const float2*>(base + 128);
    float2 c1r0 = *reinterpret_cast<const float2*>(base + CH_STRIDE);
    float2 c1r1 = *reinterpret_cast<const float2*>(base + CH_STRIDE + 128);
    float2 c2r0 = *reinterpret_cast<const float2*>(base + 2 * CH_STRIDE);
    float2 c2r1 = *reinterpret_cast<const float2*>(base + 2 * CH_STRIDE + 128);

    float a  = c0r0.x + c1r0.x + c2r0.x;
    float s1 = c0r0.y + c1r1.x;
    float s2 = c0r1.x + c2r1.y;
    float s3 = c0r1.y;
    float s4 = c1r0.y + c2r1.x;
    float s5 = c1r1.y + c2r0.y;

    float a1  = a + s1;          // A+s1
    float a2  = a + s2;          // A+s2
    float s45 = s4 + s5;

    float sum = 6.0f * __cosf(a);
    sum += __cosf(a1);
    sum += __cosf(a2);
    sum += __cosf(a + s3);
    sum += __cosf(a + s4);
    sum += __cosf(a + s5);
    sum += __cosf(a1 + s3);             // a+s1+s3
    sum += __cosf(a2 + s5);             // a+s2+s5
    sum += __cosf(a2 + s3 + s4);        // a+s2+s3+s4
    sum += __cosf(a1 + s45);            // a+s1+s4+s5
    sum += __cosf(a1 + s2 + s3 + s45);  // a+all

    out[tid] = sum * 0.0625f;
}

extern "C" void kernel_launch(void* const* d_in, const int* in_sizes, int n_in,
                              void* d_out, int out_size) {
    const float* x = (const float*)d_in[0];   // [32,3,128,128] float32
    float* out = (float*)d_out;               // [32,1,64,64] float32
    mqcnn_kernel<<<N_OUT / 256, 256>>>(x, out);
}

// round 7
// speedup vs baseline: 1.3544x; 1.0097x over previous
#include <cuda_runtime.h>
#include <cuda_bf16.h>

// MQCNN layer, closed form (R0 derivation):
// Wires 0-3 get H -> uniform superposition over 16 control branches; the 12
// controlled-RY on wire 4 compose additively per branch; H + 24 controlled-U3
// act only on wires 5,6 and preserve the wire-4 marginal (U3_w is dead).
// <Z>_4 = (1/16) sum_b cos(theta_b) = 11 distinct cosines:
// z = (6cos(a) + cos(a+s1)+cos(a+s2)+cos(a+s3)+cos(a+s4)+cos(a+s5)
//    + cos(a+s1+s3)+cos(a+s2+s5)+cos(a+s2+s3+s4)+cos(a+s1+s4+s5)
//    + cos(a+s1+s2+s3+s4+s5)) / 16
//
// R7 (terminal): R1-R6 established a hard ~5us kernel floor (launch/ramp
// overhead + one memory round trip), invariant across occ 21-71%, MLP 3-12,
// 2x instruction count. Best shape: grid 512 x block 256, 1 output/thread,
// 6x LDG.64, no bounds check. This round: explicit binary-tree accumulation
// (dependency depth 10 FADDs -> 4) and one fewer IMAD in indexing.

#define CH_STRIDE (128 * 128)
#define N_OUT (32 * 64 * 64)

__global__ __launch_bounds__(256) void mqcnn_kernel(
    const float* __restrict__ x, float* __restrict__ out)
{
    int tid = blockIdx.x * blockDim.x + threadIdx.x;

    // offset of x[b,0,2j,2k] where tid = b*4096 + j*64 + k:
    //   b*49152 + j*256 + 2k = (tid>>12)*32768 + (tid>>6)*256 + (tid&63)*2
    int off = ((tid >> 12) << 15) + ((tid >> 6) << 8) + ((tid & 63) << 1);
    const float* base = x + off;

    float2 c0r0 = *reinterpret_cast<const float2*>(base);
    float2 c0r1 = *reinterpret_cast<const float2*>(base + 128);
    float2 c1r0 = *reinterpret_cast<const float2*>(base + CH_STRIDE);
    float2 c1r1 = *reinterpret_cast<const float2*>(base + CH_STRIDE + 128);
    float2 c2r0 = *reinterpret_cast<const float2*>(base + 2 * CH_STRIDE);
    float2 c2r1 = *reinterpret_cast<const float2*>(base + 2 * CH_STRIDE + 128);

    float a  = c0r0.x + c1r0.x + c2r0.x;
    float s1 = c0r0.y + c1r1.x;
    float s2 = c0r1.x + c2r1.y;
    float s3 = c0r1.y;
    float s4 = c1r0.y + c2r1.x;
    float s5 = c1r1.y + c2r0.y;

    float a1  = a + s1;
    float a2  = a + s2;
    float s45 = s4 + s5;

    // 11 independent MUFU.COS
    float t0  = __cosf(a);                  // weight 6
    float t1  = __cosf(a1);
    float t2  = __cosf(a2);
    float t3  = __cosf(a + s3);
    float t4  = __cosf(a + s4);
    float t5  = __cosf(a + s5);
    float t6  = __cosf(a1 + s3);            // a+s1+s3
    float t7  = __cosf(a2 + s5);            // a+s2+s5
    float t8  = __cosf(a2 + s3 + s4);       // a+s2+s3+s4
    float t9  = __cosf(a1 + s45);           // a+s1+s4+s5
    float t10 = __cosf(a1 + s2 + s3 + s45); // a+all

    // balanced reduction (depth 4 + final FMA)
    float p0 = t1 + t2;
    float p1 = t3 + t4;
    float p2 = t5 + t6;
    float p3 = t7 + t8;
    float p4 = t9 + t10;
    float q0 = p0 + p1;
    float q1 = p2 + p3;
    float r0 = q0 + q1;
    float r1 = p4 + r0;
    float sum = fmaf(6.0f, t0, r1);

    out[tid] = sum * 0.0625f;
}

extern "C" void kernel_launch(void* const* d_in, const int* in_sizes, int n_in,
                              void* d_out, int out_size) {
    const float* x = (const float*)d_in[0];   // [32,3,128,128] float32
    float* out = (float*)d_out;               // [32,1,64,64] float32
    mqcnn_kernel<<<N_OUT / 256, 256>>>(x, out);
}